// round 6
// baseline (speedup 1.0000x reference)
#include <cuda_runtime.h>

// out[i] = 2 * in[i], N = 100 floats (25 float4). Launch-latency-bound:
// 800 B of traffic vs ~3.3 us fixed in-kernel overhead + ~1.2 us graph
// dispatch. This is the best-measured configuration (R2, 4.544 us wall):
// - 25 threads, one LDG.128 + 4x FMUL + STG.128 each; HW lane-masks the
//   partial warp so there is zero predication in SASS.
// - st.global.cs streaming store: skip L2-allocate bookkeeping (the one
//   change that measurably beat the baseline, 5.6 -> 4.54 us).
// - load default-cached so the input stays L2-resident across replays.
__global__ void __launch_bounds__(32, 1) mul2_kernel(const float4* __restrict__ in,
                                                     float4* __restrict__ out) {
    int i = threadIdx.x;           // 0..24
    float4 v = __ldg(&in[i]);
    v.x *= 2.0f; v.y *= 2.0f; v.z *= 2.0f; v.w *= 2.0f;
    asm volatile("st.global.cs.v4.f32 [%0], {%1, %2, %3, %4};"
                 :: "l"(&out[i]), "f"(v.x), "f"(v.y), "f"(v.z), "f"(v.w)
                 : "memory");
}

extern "C" void kernel_launch(void* const* d_in, const int* in_sizes, int n_in,
                              void* d_out, int out_size) {
    const float4* in = (const float4*)d_in[0];
    float4* out = (float4*)d_out;
    mul2_kernel<<<1, 25>>>(in, out);
}

// round 7
// speedup vs baseline: 1.1111x; 1.1111x over previous
#include <cuda_runtime.h>

// out[i] = 2 * in[i], N = 100 floats (50 float2). Launch-latency-bound:
// measured jitter (+-0.5us) exceeds any in-body lever. This variant probes
// the last untried structure: 2 warps (50 threads x float2) so two SMSP
// schedulers issue the load streams in parallel, halving per-warp L1tex
// queue depth. Streaming store kept (only change that ever measurably won).
__global__ void __launch_bounds__(64, 1) mul2_kernel(const float2* __restrict__ in,
                                                     float2* __restrict__ out) {
    int i = threadIdx.x;           // 0..49; lanes 50..63 of warp 1 are masked
    if (i < 50) {
        float2 v = __ldg(&in[i]);
        v.x *= 2.0f; v.y *= 2.0f;
        asm volatile("st.global.cs.v2.f32 [%0], {%1, %2};"
                     :: "l"(&out[i]), "f"(v.x), "f"(v.y)
                     : "memory");
    }
}

extern "C" void kernel_launch(void* const* d_in, const int* in_sizes, int n_in,
                              void* d_out, int out_size) {
    const float2* in = (const float2*)d_in[0];
    float2* out = (float2*)d_out;
    mul2_kernel<<<1, 64>>>(in, out);
}